// round 1
// baseline (speedup 1.0000x reference)
#include <cuda_runtime.h>
#include <cuda_bf16.h>

#define PHp 7
#define PWp 7
#define SRs 2
#define SCALEc 0.0625f
#define Bc 2
#define Cc 256
#define Hc 100
#define Wc 152
#define Rc 1024
#define CHUNK 4

__global__ void __launch_bounds__(256) roialign_kernel(
    const float* __restrict__ feat,
    const float* __restrict__ rois,
    float* __restrict__ out)
{
    const int CG = Cc / CHUNK;                       // 64 channel groups
    int n = blockIdx.x * blockDim.x + threadIdx.x;
    if (n >= Rc * CG * PHp * PWp) return;

    int pw = n % PWp;
    int ph = (n / PWp) % PHp;
    int cg = (n / (PWp * PHp)) % CG;
    int r  = n / (PWp * PHp * CG);

    const float* roi = rois + r * 5;
    int   b   = (int)roi[0];
    float rsw = roi[1] * SCALEc;
    float rsh = roi[2] * SCALEc;
    float rew = roi[3] * SCALEc;
    float reh = roi[4] * SCALEc;
    float roi_w = fmaxf(rew - rsw, 1.0f);
    float roi_h = fmaxf(reh - rsh, 1.0f);
    float bin_h = roi_h * (1.0f / PHp);
    float bin_w = roi_w * (1.0f / PWp);

    float acc[CHUNK];
    #pragma unroll
    for (int j = 0; j < CHUNK; j++) acc[j] = 0.0f;

    const int HW = Hc * Wc;
    const float* fb = feat + ((size_t)b * Cc + (size_t)cg * CHUNK) * HW;

    #pragma unroll
    for (int iy = 0; iy < SRs; iy++) {
        float y = rsh + ((float)ph + ((float)iy + 0.5f) * (1.0f / SRs)) * bin_h;
        #pragma unroll
        for (int ix = 0; ix < SRs; ix++) {
            float x = rsw + ((float)pw + ((float)ix + 0.5f) * (1.0f / SRs)) * bin_w;

            bool valid = (y >= -1.0f) && (y <= (float)Hc) &&
                         (x >= -1.0f) && (x <= (float)Wc);
            if (!valid) continue;

            float yc = fminf(fmaxf(y, 0.0f), (float)(Hc - 1));
            float xc = fminf(fmaxf(x, 0.0f), (float)(Wc - 1));
            int ylo = (int)floorf(yc);
            int xlo = (int)floorf(xc);
            int yhi = min(ylo + 1, Hc - 1);
            int xhi = min(xlo + 1, Wc - 1);
            float ly = yc - (float)ylo;
            float lx = xc - (float)xlo;
            float hy = 1.0f - ly, hx = 1.0f - lx;
            float w11 = hy * hx, w12 = hy * lx;
            float w21 = ly * hx, w22 = ly * lx;
            int i11 = ylo * Wc + xlo;
            int i12 = ylo * Wc + xhi;
            int i21 = yhi * Wc + xlo;
            int i22 = yhi * Wc + xhi;

            #pragma unroll
            for (int j = 0; j < CHUNK; j++) {
                const float* fc = fb + (size_t)j * HW;
                float v = w11 * __ldg(fc + i11);
                v = fmaf(w12, __ldg(fc + i12), v);
                v = fmaf(w21, __ldg(fc + i21), v);
                v = fmaf(w22, __ldg(fc + i22), v);
                acc[j] += v;
            }
        }
    }

    float* op = out + (((size_t)r * Cc + (size_t)cg * CHUNK) * PHp + ph) * PWp + pw;
    #pragma unroll
    for (int j = 0; j < CHUNK; j++)
        op[(size_t)j * (PHp * PWp)] = acc[j] * (1.0f / (SRs * SRs));
}

extern "C" void kernel_launch(void* const* d_in, const int* in_sizes, int n_in,
                              void* d_out, int out_size)
{
    const float* feat = (const float*)d_in[0];
    const float* rois = (const float*)d_in[1];
    float* out = (float*)d_out;

    const int total = Rc * (Cc / CHUNK) * PHp * PWp;   // 3,211,264 threads
    const int threads = 256;
    const int blocks = (total + threads - 1) / threads;
    roialign_kernel<<<blocks, threads>>>(feat, rois, out);
}

// round 2
// speedup vs baseline: 1.6650x; 1.6650x over previous
#include <cuda_runtime.h>
#include <cuda_bf16.h>

#define PHp 7
#define PWp 7
#define SRs 2
#define SCALEc 0.0625f
#define Bc 2
#define Cc 256
#define Hc 100
#define Wc 152
#define Rc 1024
#define HWc (Hc * Wc)          // 15200

// NHWC scratch: [B][H*W][C] = 2*15200*256 floats = 31.1 MB
__device__ float g_nhwc[(size_t)Bc * HWc * Cc];

// ---------------- Phase 1: NCHW -> NHWC transpose ----------------
// Treat as per-batch 2D transpose [C, HW] -> [HW, C]. 32x32 tiles.
__global__ void __launch_bounds__(256) transpose_kernel(const float* __restrict__ in)
{
    __shared__ float tile[32][33];
    int s0 = blockIdx.x * 32;           // HW tile (475 tiles, exact)
    int c0 = blockIdx.y * 32;           // C tile (8 tiles, exact)
    int b  = blockIdx.z;

    const float* ib = in + (size_t)b * Cc * HWc;
    float* ob = g_nhwc + (size_t)b * HWc * Cc;

    int s = s0 + threadIdx.x;
    #pragma unroll
    for (int j = threadIdx.y; j < 32; j += 8)
        tile[j][threadIdx.x] = ib[(size_t)(c0 + j) * HWc + s];
    __syncthreads();

    int c = c0 + threadIdx.x;
    #pragma unroll
    for (int j = threadIdx.y; j < 32; j += 8)
        ob[(size_t)(s0 + j) * Cc + c] = tile[threadIdx.x][j];
}

// ---------------- Phase 2: RoIAlign on NHWC ----------------
// One block per (roi, channel-half). 256 threads:
//   c4 = tid & 31  -> float4 channel group (32 groups * 4 = 128 channels)
//   bs = tid >> 5  -> bin stride start (8 parallel bin streams, 49 bins)
// Gathers: each corner load is a warp-coalesced 512B LDG.128 burst.
// Output staged in smem, copied out contiguous & coalesced.
#define CPAD 132   // 128 channels + pad (multiple of 4 for STS.128 alignment)

__global__ void __launch_bounds__(256) roialign_nhwc_kernel(
    const float* __restrict__ rois,
    float* __restrict__ out)
{
    __shared__ float s[PHp * PWp * CPAD];   // 49*132*4 = 25,872 B

    int r    = blockIdx.x >> 1;
    int half = blockIdx.x & 1;
    int tid  = threadIdx.x;
    int c4   = tid & 31;
    int bs   = tid >> 5;

    const float* roi = rois + r * 5;
    int   b   = (int)roi[0];
    float rsw = roi[1] * SCALEc;
    float rsh = roi[2] * SCALEc;
    float roi_w = fmaxf(roi[3] * SCALEc - rsw, 1.0f);
    float roi_h = fmaxf(roi[4] * SCALEc - rsh, 1.0f);
    float bin_h = roi_h * (1.0f / PHp);
    float bin_w = roi_w * (1.0f / PWp);

    const float* fb = g_nhwc + (size_t)b * HWc * Cc + (half * 128 + c4 * 4);

    for (int bin = bs; bin < PHp * PWp; bin += 8) {
        int ph = bin / PWp;
        int pw = bin - ph * PWp;

        float ax = 0.f, ay = 0.f, az = 0.f, aw = 0.f;

        #pragma unroll
        for (int iy = 0; iy < SRs; iy++) {
            float y = rsh + ((float)ph + ((float)iy + 0.5f) * (1.0f / SRs)) * bin_h;
            #pragma unroll
            for (int ix = 0; ix < SRs; ix++) {
                float x = rsw + ((float)pw + ((float)ix + 0.5f) * (1.0f / SRs)) * bin_w;

                bool valid = (y >= -1.0f) && (y <= (float)Hc) &&
                             (x >= -1.0f) && (x <= (float)Wc);
                if (!valid) continue;

                float yc = fminf(fmaxf(y, 0.0f), (float)(Hc - 1));
                float xc = fminf(fmaxf(x, 0.0f), (float)(Wc - 1));
                int ylo = (int)floorf(yc);
                int xlo = (int)floorf(xc);
                int yhi = min(ylo + 1, Hc - 1);
                int xhi = min(xlo + 1, Wc - 1);
                float ly = yc - (float)ylo;
                float lx = xc - (float)xlo;
                float hy = 1.0f - ly, hx = 1.0f - lx;
                float w11 = hy * hx, w12 = hy * lx;
                float w21 = ly * hx, w22 = ly * lx;

                const float4 v11 = *(const float4*)(fb + (size_t)(ylo * Wc + xlo) * Cc);
                const float4 v12 = *(const float4*)(fb + (size_t)(ylo * Wc + xhi) * Cc);
                const float4 v21 = *(const float4*)(fb + (size_t)(yhi * Wc + xlo) * Cc);
                const float4 v22 = *(const float4*)(fb + (size_t)(yhi * Wc + xhi) * Cc);

                ax = fmaf(w11, v11.x, fmaf(w12, v12.x, fmaf(w21, v21.x, fmaf(w22, v22.x, ax))));
                ay = fmaf(w11, v11.y, fmaf(w12, v12.y, fmaf(w21, v21.y, fmaf(w22, v22.y, ay))));
                az = fmaf(w11, v11.z, fmaf(w12, v12.z, fmaf(w21, v21.z, fmaf(w22, v22.z, az))));
                aw = fmaf(w11, v11.w, fmaf(w12, v12.w, fmaf(w21, v21.w, fmaf(w22, v22.w, aw))));
            }
        }

        float4 acc = make_float4(ax * 0.25f, ay * 0.25f, az * 0.25f, aw * 0.25f);
        *(float4*)(s + bin * CPAD + c4 * 4) = acc;   // conflict-free STS.128
    }
    __syncthreads();

    // Coalesced copy-out: out[r][c][ph][pw], this block's 128*49 floats are contiguous.
    float* ob = out + (size_t)r * (Cc * PHp * PWp) + (size_t)half * 128 * PHp * PWp;
    #pragma unroll 4
    for (int i = tid; i < 128 * PHp * PWp; i += 256) {
        int c = i / (PHp * PWp);
        int bin = i - c * (PHp * PWp);
        ob[i] = s[bin * CPAD + c];
    }
}

extern "C" void kernel_launch(void* const* d_in, const int* in_sizes, int n_in,
                              void* d_out, int out_size)
{
    const float* feat = (const float*)d_in[0];
    const float* rois = (const float*)d_in[1];
    float* out = (float*)d_out;

    dim3 tg(HWc / 32, Cc / 32, Bc);        // 475 x 8 x 2
    dim3 tb(32, 8, 1);
    transpose_kernel<<<tg, tb>>>(feat);

    roialign_nhwc_kernel<<<Rc * 2, 256>>>(rois, out);
}